// round 2
// baseline (speedup 1.0000x reference)
#include <cuda_runtime.h>
#include <math.h>

// ---------------------------------------------------------------------------
// CosformerAttention: bsz=2, L=1024, E=512, H=8, D=64
// Flat row-major view: X[2048][512], row r = l*2 + b  (pure reshape in ref).
// Pipeline:
//   1) qkv_kernel : Q=relu(X Wq^T+bq), K=relu(X Wk^T+bk), V=X Wv^T+bv  (fused)
//   2) chunksum   : per 128-chunk  KV_c[128][64] = sum k_exp (x) v ; z_c[128]
//   3) scan       : exclusive prefix over the 8 chunks of each sequence
//   4) chunkattn  : W=(QK^T)*cosdiff masked;  qkv = W V + Qexp S_prev;
//                   denom = rowsum(W) + Qexp z_prev ; attn = qkv/denom
//   5) out_kernel : out = attn Wo^T + bo
// ---------------------------------------------------------------------------

constexpr int E_DIM  = 512;
constexpr int NROWS  = 2048;   // L * bsz
constexpr int CHUNK  = 128;
constexpr int NCHUNK = 128;    // 16 sequences * 8 chunks
constexpr float ANG  = 1.5707963267948966f / 1024.0f;  // (pi/2)/L
constexpr float EPSV = 1e-6f;

// scratch (device globals: allocation-free rule)
__device__ __align__(16) float g_QKV[NROWS * 1536];        // [2048][1536]: Q|K|V
__device__ __align__(16) float g_attn[NROWS * E_DIM];      // [2048][512]
__device__ __align__(16) float g_state[NCHUNK * 128 * 64]; // per-chunk KV state
__device__ __align__(16) float g_z[NCHUNK * 128];          // per-chunk k-sum state

// ---------------------------------------------------------------------------
// Generic 128x128 NT GEMM tile: C = A[2048xK=512] * B^T + bias  (K-major smem)
// ---------------------------------------------------------------------------
__device__ __forceinline__ void gemm_tile(
    const float* __restrict__ A,
    const float* __restrict__ B, int brow0,
    const float* __restrict__ bias, int bidx0,
    float* __restrict__ C, int ldc, int ccol0,
    int m0, bool do_relu)
{
    __shared__ float sA[8][128];
    __shared__ float sB[8][128];
    const int tid  = threadIdx.x;       // 256
    const int tx   = tid & 15;
    const int ty   = tid >> 4;
    const int lrow = tid >> 1;          // 0..127
    const int lkv  = (tid & 1) << 2;    // 0 or 4

    float acc[8][8];
#pragma unroll
    for (int i = 0; i < 8; i++)
#pragma unroll
        for (int j = 0; j < 8; j++) acc[i][j] = 0.f;

    const float* Aptr = A + (size_t)(m0 + lrow) * E_DIM + lkv;
    const float* Bptr = B + (size_t)(brow0 + lrow) * E_DIM + lkv;

    for (int k0 = 0; k0 < E_DIM; k0 += 8) {
        float4 av = *(const float4*)(Aptr + k0);
        float4 bv = *(const float4*)(Bptr + k0);
        __syncthreads();
        sA[lkv + 0][lrow] = av.x; sA[lkv + 1][lrow] = av.y;
        sA[lkv + 2][lrow] = av.z; sA[lkv + 3][lrow] = av.w;
        sB[lkv + 0][lrow] = bv.x; sB[lkv + 1][lrow] = bv.y;
        sB[lkv + 2][lrow] = bv.z; sB[lkv + 3][lrow] = bv.w;
        __syncthreads();
#pragma unroll
        for (int kk = 0; kk < 8; kk++) {
            float a[8], b[8];
            *(float4*)&a[0] = *(const float4*)&sA[kk][ty * 4];
            *(float4*)&a[4] = *(const float4*)&sA[kk][64 + ty * 4];
            *(float4*)&b[0] = *(const float4*)&sB[kk][tx * 4];
            *(float4*)&b[4] = *(const float4*)&sB[kk][64 + tx * 4];
#pragma unroll
            for (int i = 0; i < 8; i++)
#pragma unroll
                for (int j = 0; j < 8; j++)
                    acc[i][j] = fmaf(a[i], b[j], acc[i][j]);
        }
    }
#pragma unroll
    for (int i = 0; i < 8; i++) {
        int ri = (i < 4) ? (ty * 4 + i) : (64 + ty * 4 + (i - 4));
        int r  = m0 + ri;
#pragma unroll
        for (int j = 0; j < 8; j++) {
            int cj = (j < 4) ? (tx * 4 + j) : (64 + tx * 4 + (j - 4));
            float v = acc[i][j] + bias[bidx0 + cj];
            if (do_relu) v = fmaxf(v, 0.f);
            C[(size_t)r * ldc + ccol0 + cj] = v;
        }
    }
}

// ---- fused QKV projection: grid (16, 12) ----------------------------------
__global__ __launch_bounds__(256) void qkv_kernel(
    const float* __restrict__ X,
    const float* __restrict__ Wq, const float* __restrict__ bq,
    const float* __restrict__ Wk, const float* __restrict__ bk,
    const float* __restrict__ Wv, const float* __restrict__ bv)
{
    int m0   = blockIdx.x * 128;
    int ng   = blockIdx.y * 128;     // 0..1535
    int sect = ng >> 9;              // 0:Q 1:K 2:V
    int nl   = ng & 511;
    const float* W    = (sect == 0) ? Wq : (sect == 1) ? Wk : Wv;
    const float* bias = (sect == 0) ? bq : (sect == 1) ? bk : bv;
    gemm_tile(X, W, nl, bias, nl, g_QKV, 1536, ng, m0, sect < 2);
}

// ---- output projection: grid (16, 4) --------------------------------------
__global__ __launch_bounds__(256) void out_kernel(
    const float* __restrict__ Wo, const float* __restrict__ bo,
    float* __restrict__ out)
{
    int m0 = blockIdx.x * 128;
    int n0 = blockIdx.y * 128;
    gemm_tile(g_attn, Wo, n0, bo, n0, out, E_DIM, n0, m0, false);
}

// ---------------------------------------------------------------------------
// Per-chunk sums: KV_c[dd][m] = sum_l k_exp[l][dd] * v[l][m];  z_c[dd]
// grid: 128 blocks, 256 threads
// ---------------------------------------------------------------------------
__global__ __launch_bounds__(256) void chunksum_kernel()
{
    int c  = blockIdx.x;
    int n  = c >> 3, cc = c & 7;
    int b  = n >> 3, h  = n & 7;
    int tid = threadIdx.x;

    __shared__ float kb[8][64], vb[8][64], sl[8], clv[8];

    const int dd = tid >> 1;          // 0..127 (expanded k index)
    const int mg = (tid & 1) << 5;    // 0 or 32 (value column group)
    float acc[32];
#pragma unroll
    for (int m = 0; m < 32; m++) acc[m] = 0.f;
    float zacc = 0.f;

    const int ll  = tid >> 5;         // 0..7   (row within tile)
    const int off = (tid & 31) << 2;  // 0..124 (float4 offset, k then v)

    for (int l0 = 0; l0 < CHUNK; l0 += 8) {
        __syncthreads();
        {
            int lg  = cc * CHUNK + l0 + ll;
            int r   = lg * 2 + b;
            int col = (off < 64) ? (512 + h * 64 + off) : (1024 + h * 64 + (off - 64));
            float4 val = *(const float4*)&g_QKV[(size_t)r * 1536 + col];
            if (off < 64) *(float4*)&kb[ll][off]      = val;
            else          *(float4*)&vb[ll][off - 64] = val;
            if (tid < 8) {
                float th = ANG * (float)(cc * CHUNK + l0 + tid + 1);
                sl[tid]  = sinf(th);
                clv[tid] = cosf(th);
            }
        }
        __syncthreads();
#pragma unroll
        for (int q = 0; q < 8; q++) {
            float ke = (dd < 64) ? (sl[q] * kb[q][dd]) : (clv[q] * kb[q][dd - 64]);
            zacc += ke;
#pragma unroll
            for (int m = 0; m < 32; m++)
                acc[m] = fmaf(ke, vb[q][mg + m], acc[m]);
        }
    }
    float* st = &g_state[(size_t)c * 8192 + (size_t)dd * 64 + mg];
#pragma unroll
    for (int m = 0; m < 32; m += 4)
        *(float4*)&st[m] = make_float4(acc[m], acc[m+1], acc[m+2], acc[m+3]);
    if (mg == 0) g_z[c * 128 + dd] = zacc;
}

// ---- exclusive prefix over chunks of each sequence: grid (16, 33) ---------
__global__ __launch_bounds__(256) void scan_kernel()
{
    int n = blockIdx.x;
    if (blockIdx.y < 32) {
        int e = blockIdx.y * 256 + threadIdx.x;   // 0..8191
        float run = 0.f;
        for (int cc = 0; cc < 8; cc++) {
            size_t idx = (size_t)(n * 8 + cc) * 8192 + e;
            float t = g_state[idx];
            g_state[idx] = run;
            run += t;
        }
    } else if (threadIdx.x < 128) {
        int e = threadIdx.x;
        float run = 0.f;
        for (int cc = 0; cc < 8; cc++) {
            int idx = (n * 8 + cc) * 128 + e;
            float t = g_z[idx];
            g_z[idx] = run;
            run += t;
        }
    }
}

// ---------------------------------------------------------------------------
// Per-chunk attention. grid: 128 blocks, 256 threads, ~167 KB dynamic smem
// ---------------------------------------------------------------------------
constexpr int TS = 132;  // sQt/sKt row stride (k-major, float4-aligned)
constexpr int VS = 68;   // sV row stride
constexpr int WS = 129;  // sW row stride (odd -> conflict-free column reads)
constexpr int SMEM_FLOATS = 64*TS + 64*TS + 128*VS + 128*WS + 4*128;
constexpr int SMEM_BYTES  = SMEM_FLOATS * 4;

__global__ __launch_bounds__(256) void chunkattn_kernel()
{
    extern __shared__ float sm[];
    float* sQt  = sm;                    // [64][TS]  transposed Q (k-major)
    float* sKt  = sQt + 64 * TS;         // [64][TS]  transposed K; reused as sS
    float* sV   = sKt + 64 * TS;         // [128][VS]
    float* sW   = sV + 128 * VS;         // [128][WS] masked weighted scores
    float* ssin = sW + 128 * WS;         // [128]
    float* scos = ssin + 128;            // [128]
    float* sden = scos + 128;            // [128]
    float* szp  = sden + 128;            // [128]  z_prev

    int c  = blockIdx.x;
    int n  = c >> 3, cc = c & 7;
    int b  = n >> 3, h  = n & 7;
    int tid = threadIdx.x;

    // ---- load Q,K (transposed) and V; column-major thread mapping ----
#pragma unroll
    for (int i = 0; i < 8; i++) {
        int f4 = tid + i * 256;          // 0..2047
        int l  = f4 & 127;
        int kv = (f4 >> 7) << 2;         // 0,4,...,60
        int r  = (cc * CHUNK + l) * 2 + b;
        const float* base = &g_QKV[(size_t)r * 1536 + h * 64 + kv];
        float4 qv = *(const float4*)(base);
        float4 k4 = *(const float4*)(base + 512);
        float4 vv = *(const float4*)(base + 1024);
        sQt[(kv + 0) * TS + l] = qv.x; sQt[(kv + 1) * TS + l] = qv.y;
        sQt[(kv + 2) * TS + l] = qv.z; sQt[(kv + 3) * TS + l] = qv.w;
        sKt[(kv + 0) * TS + l] = k4.x; sKt[(kv + 1) * TS + l] = k4.y;
        sKt[(kv + 2) * TS + l] = k4.z; sKt[(kv + 3) * TS + l] = k4.w;
        *(float4*)&sV[l * VS + kv] = vv;
    }
    if (tid < 128) {
        float th = ANG * (float)(cc * CHUNK + tid + 1);
        ssin[tid] = sinf(th);
        scos[tid] = cosf(th);
        szp[tid]  = g_z[c * 128 + tid];
    }
    __syncthreads();

    // ---- Phase A: W[l][j] = (q_l . k_j) * cos(th_l - th_j), masked j<=l ----
    {
        int tx = tid & 15, ty = tid >> 4;
        float accW[8][8];
#pragma unroll
        for (int i = 0; i < 8; i++)
#pragma unroll
            for (int j = 0; j < 8; j++) accW[i][j] = 0.f;

        for (int kk = 0; kk < 64; kk++) {
            float a[8], bb[8];
            *(float4*)&a[0]  = *(const float4*)&sQt[kk * TS + ty * 4];
            *(float4*)&a[4]  = *(const float4*)&sQt[kk * TS + 64 + ty * 4];
            *(float4*)&bb[0] = *(const float4*)&sKt[kk * TS + tx * 4];
            *(float4*)&bb[4] = *(const float4*)&sKt[kk * TS + 64 + tx * 4];
#pragma unroll
            for (int i = 0; i < 8; i++)
#pragma unroll
                for (int j = 0; j < 8; j++)
                    accW[i][j] = fmaf(a[i], bb[j], accW[i][j]);
        }
        float slv[8], clvv[8], sjv[8], cjv[8];
#pragma unroll
        for (int i = 0; i < 8; i++) {
            int ri = (i < 4) ? (ty * 4 + i) : (64 + ty * 4 + (i - 4));
            int cj = (i < 4) ? (tx * 4 + i) : (64 + tx * 4 + (i - 4));
            slv[i] = ssin[ri]; clvv[i] = scos[ri];
            sjv[i] = ssin[cj]; cjv[i]  = scos[cj];
        }
#pragma unroll
        for (int i = 0; i < 8; i++) {
            int l = (i < 4) ? (ty * 4 + i) : (64 + ty * 4 + (i - 4));
#pragma unroll
            for (int j = 0; j < 8; j++) {
                int jj = (j < 4) ? (tx * 4 + j) : (64 + tx * 4 + (j - 4));
                float w = (jj <= l)
                        ? accW[i][j] * (slv[i] * sjv[j] + clvv[i] * cjv[j])
                        : 0.f;
                sW[l * WS + jj] = w;
            }
        }
    }
    __syncthreads();

    // ---- Phase B: qkv = W V + Qexp S_prev ; denom ; write attn ----
    {
        int l  = tid & 127;
        int mh = tid >> 7;
        int m0 = mh << 5;
        float acc2[32];
#pragma unroll
        for (int m = 0; m < 32; m++) acc2[m] = 0.f;
        float wsum = 0.f, dsum = 0.f;
        float sl = ssin[l], cl = scos[l];

        // intra-chunk: W @ V
#pragma unroll 2
        for (int j = 0; j < 128; j++) {
            float w = sW[l * WS + j];
            wsum += w;
#pragma unroll
            for (int m = 0; m < 32; m += 4) {
                float4 v4 = *(const float4*)&sV[j * VS + m0 + m];
                acc2[m + 0] = fmaf(w, v4.x, acc2[m + 0]);
                acc2[m + 1] = fmaf(w, v4.y, acc2[m + 1]);
                acc2[m + 2] = fmaf(w, v4.z, acc2[m + 2]);
                acc2[m + 3] = fmaf(w, v4.w, acc2[m + 3]);
            }
        }

        // cross-chunk: Qexp @ S_prev  (stage S into sKt region, 64 dd at a time)
        float* sS = sKt;
        for (int t0 = 0; t0 < 128; t0 += 64) {
            __syncthreads();
#pragma unroll
            for (int i2 = 0; i2 < 4; i2++) {
                int f4  = tid + i2 * 256;       // 0..1023
                int ddl = f4 >> 4;              // 0..63
                int mv  = (f4 & 15) << 2;
                *(float4*)&sS[ddl * 64 + mv] =
                    *(const float4*)&g_state[(size_t)c * 8192 + (size_t)(t0 + ddl) * 64 + mv];
            }
            __syncthreads();
#pragma unroll 2
            for (int dd = 0; dd < 64; dd++) {
                int ddg  = t0 + dd;
                float qe = ((ddg < 64) ? sl : cl) * sQt[(ddg & 63) * TS + l];
                dsum = fmaf(qe, szp[ddg], dsum);
#pragma unroll
                for (int m = 0; m < 32; m += 4) {
                    float4 s4 = *(const float4*)&sS[dd * 64 + m0 + m];
                    acc2[m + 0] = fmaf(qe, s4.x, acc2[m + 0]);
                    acc2[m + 1] = fmaf(qe, s4.y, acc2[m + 1]);
                    acc2[m + 2] = fmaf(qe, s4.z, acc2[m + 2]);
                    acc2[m + 3] = fmaf(qe, s4.w, acc2[m + 3]);
                }
            }
        }

        if (mh == 0) sden[l] = fmaxf(wsum + dsum, EPSV);
        __syncthreads();
        float inv = 1.0f / sden[l];
        int r = (cc * CHUNK + l) * 2 + b;
        float* dst = &g_attn[(size_t)r * E_DIM + h * 64 + m0];
#pragma unroll
        for (int m = 0; m < 32; m += 4) {
            *(float4*)&dst[m] = make_float4(acc2[m] * inv, acc2[m + 1] * inv,
                                            acc2[m + 2] * inv, acc2[m + 3] * inv);
        }
    }
}

// ---------------------------------------------------------------------------
extern "C" void kernel_launch(void* const* d_in, const int* in_sizes, int n_in,
                              void* d_out, int out_size)
{
    const float* query = (const float*)d_in[0];
    const float* Wq = (const float*)d_in[1];
    const float* bq = (const float*)d_in[2];
    const float* Wk = (const float*)d_in[3];
    const float* bk = (const float*)d_in[4];
    const float* Wv = (const float*)d_in[5];
    const float* bv = (const float*)d_in[6];
    const float* Wo = (const float*)d_in[7];
    const float* bo = (const float*)d_in[8];
    float* out = (float*)d_out;

    cudaFuncSetAttribute(chunkattn_kernel,
                         cudaFuncAttributeMaxDynamicSharedMemorySize, SMEM_BYTES);

    qkv_kernel<<<dim3(16, 12), 256>>>(query, Wq, bq, Wk, bk, Wv, bv);
    chunksum_kernel<<<128, 256>>>();
    scan_kernel<<<dim3(16, 33), 256>>>();
    chunkattn_kernel<<<128, 256, SMEM_BYTES>>>();
    out_kernel<<<dim3(16, 4), 256>>>(Wo, bo, out);
}

// round 4
// speedup vs baseline: 1.6865x; 1.6865x over previous
#include <cuda_runtime.h>
#include <cuda_bf16.h>
#include <math.h>
#include <stdint.h>

// ---------------------------------------------------------------------------
// CosformerAttention: bsz=2, L=1024, E=512, H=8, D=64
// Flat row-major view: X[2048][512], row r = l*2 + b  (pure reshape in ref).
//   1) mma_qkv : Q=relu(X Wq^T+bq), K=relu(X Wk^T+bk), V=X Wv^T+bv  [HMMA bf16]
//   2) chunksum: per 128-chunk  KV_c[128][64] = sum k_exp (x) v ; z_c
//   3) scan    : exclusive prefix over the 8 chunks of each sequence
//   4) chunkattn: W=(QK^T)*cosdiff masked; qkv = W V + Qexp S_prev; denom
//   5) mma_out : out = attn Wo^T + bo                               [HMMA bf16]
// GEMMs: split-bf16 (hi+lo, 3 products) mma.sync m16n8k16, fp32 accumulate.
// (tcgen05 is unavailable: harness PTX target is sm_103, not sm_103a.)
// ---------------------------------------------------------------------------

constexpr int E_DIM  = 512;
constexpr int NROWS  = 2048;   // L * bsz
constexpr int CHUNK  = 128;
constexpr int NCHUNK = 128;    // 16 sequences * 8 chunks
constexpr float ANG  = 1.5707963267948966f / 1024.0f;  // (pi/2)/L
constexpr float EPSV = 1e-6f;

// scratch (device globals: allocation-free rule)
__device__ __align__(16) float g_QKV[NROWS * 1536];        // [2048][1536]: Q|K|V
__device__ __align__(16) float g_attn[NROWS * E_DIM];      // [2048][512]
__device__ __align__(16) float g_state[NCHUNK * 128 * 64]; // per-chunk KV state
__device__ __align__(16) float g_z[NCHUNK * 128];          // per-chunk k-sum

// ---------------------------------------------------------------------------
// helpers
// ---------------------------------------------------------------------------
__device__ __forceinline__ uint32_t smem_u32(const void* p) {
    uint32_t a;
    asm("{ .reg .u64 t; cvta.to.shared.u64 t, %1; cvt.u32.u64 %0, t; }"
        : "=r"(a) : "l"(p));
    return a;
}

__device__ __forceinline__ void ldsm_x4(uint32_t& r0, uint32_t& r1,
                                        uint32_t& r2, uint32_t& r3, uint32_t a) {
    asm volatile("ldmatrix.sync.aligned.m8n8.x4.shared.b16 {%0,%1,%2,%3}, [%4];"
                 : "=r"(r0), "=r"(r1), "=r"(r2), "=r"(r3) : "r"(a));
}

__device__ __forceinline__ void mma_bf16(float* c, const uint32_t* a,
                                         uint32_t b0, uint32_t b1) {
    asm volatile(
        "mma.sync.aligned.m16n8k16.row.col.f32.bf16.bf16.f32 "
        "{%0,%1,%2,%3}, {%4,%5,%6,%7}, {%8,%9}, {%0,%1,%2,%3};"
        : "+f"(c[0]), "+f"(c[1]), "+f"(c[2]), "+f"(c[3])
        : "r"(a[0]), "r"(a[1]), "r"(a[2]), "r"(a[3]), "r"(b0), "r"(b1));
}

// split (x0,x1) into packed bf16 hi pair (returned) and lo pair (out)
__device__ __forceinline__ uint32_t split2(float x0, float x1, uint32_t& lo) {
    uint32_t hi;
    asm("cvt.rn.bf16x2.f32 %0, %1, %2;" : "=r"(hi) : "f"(x1), "f"(x0));
    float h0 = __uint_as_float(hi << 16);
    float h1 = __uint_as_float(hi & 0xFFFF0000u);
    asm("cvt.rn.bf16x2.f32 %0, %1, %2;" : "=r"(lo) : "f"(x1 - h1), "f"(x0 - h0));
    return hi;
}

// ---------------------------------------------------------------------------
// HMMA split-bf16 GEMM tile: C[128x128] = A[128x512] * W[row0..+128][512]^T + b
// smem: 2 stages x 4 arrays (AH, AL, WH, WL), each 128 rows x 64 halves,
// row stride 72 halves (144 B: 9 x 16B units, odd -> ldmatrix conflict-free)
// ---------------------------------------------------------------------------
constexpr int SROW    = 72;                     // halves per smem row
constexpr int ARR_B   = 128 * SROW * 2;         // 18432 bytes per array
constexpr int OFF_AH  = 0;
constexpr int OFF_AL  = ARR_B;
constexpr int OFF_WH  = 2 * ARR_B;
constexpr int OFF_WL  = 3 * ARR_B;
constexpr int STAGE_B = 4 * ARR_B;              // 73728
constexpr int TC_SMEM = 2 * STAGE_B;            // 147456

__device__ void tc_gemm_tile(const float* __restrict__ A, const float* __restrict__ W,
                             const float* __restrict__ bias, float* __restrict__ C,
                             int ldc, int m0, int nr0, int ccol0, bool relu)
{
    extern __shared__ char dynsm[];
    const uint32_t sbase = smem_u32(dynsm);
    const int tid  = threadIdx.x;
    const int wid  = tid >> 5, lane = tid & 31;
    const int wm   = (wid & 1) * 64;     // warp row offset in tile
    const int wn   = (wid >> 1) * 32;    // warp col offset in tile

    const float* Abase = A + (size_t)m0 * E_DIM;
    const float* Bbase = W + (size_t)nr0 * E_DIM;

    auto fill = [&](int st, int k0) {
        char* sb = dynsm + st * STAGE_B;
#pragma unroll
        for (int i = 0; i < 8; i++) {
            int idx = tid + i * 256;           // 0..2047
            int row = idx >> 4;                // 0..127
            int col = (idx & 15) * 4;          // 0..60 (halves/floats)
            float4 a = *(const float4*)(Abase + (size_t)row * E_DIM + k0 + col);
            float4 w = *(const float4*)(Bbase + (size_t)row * E_DIM + k0 + col);
            uint32_t off = (uint32_t)(row * SROW + col) * 2;   // byte offset
            uint32_t l0, l1, h0, h1;
            h0 = split2(a.x, a.y, l0); h1 = split2(a.z, a.w, l1);
            *(uint2*)(sb + OFF_AH + off) = make_uint2(h0, h1);
            *(uint2*)(sb + OFF_AL + off) = make_uint2(l0, l1);
            h0 = split2(w.x, w.y, l0); h1 = split2(w.z, w.w, l1);
            *(uint2*)(sb + OFF_WH + off) = make_uint2(h0, h1);
            *(uint2*)(sb + OFF_WL + off) = make_uint2(l0, l1);
        }
    };

    float acc[4][4][4];
#pragma unroll
    for (int i = 0; i < 4; i++)
#pragma unroll
        for (int j = 0; j < 4; j++)
#pragma unroll
            for (int q = 0; q < 4; q++) acc[i][j][q] = 0.f;

    // per-lane ldmatrix address components (byte offsets, within array)
    const uint32_t a_base = (uint32_t)((wm + (lane & 15)) * SROW + (lane >> 4) * 8) * 2;
    const uint32_t b_base = (uint32_t)((wn + (lane & 7) + ((lane >> 4) & 1) * 8) * SROW
                                       + ((lane >> 3) & 1) * 8) * 2;

    fill(0, 0);
    __syncthreads();

    for (int s = 0; s < 8; s++) {
        if (s < 7) fill((s + 1) & 1, (s + 1) * 64);   // overlap with compute

        const uint32_t stg = sbase + (s & 1) * STAGE_B;
#pragma unroll
        for (int kb16 = 0; kb16 < 4; kb16++) {
            const uint32_t koff = kb16 * 32;   // 16 halves = 32 bytes
            // --- B fragments: 4 n-tiles, hi and lo ---
            uint32_t bh[8], bl[8];
#pragma unroll
            for (int nh = 0; nh < 2; nh++) {
                uint32_t ba = stg + b_base + (uint32_t)(nh * 16 * SROW * 2) + koff;
                ldsm_x4(bh[nh*4+0], bh[nh*4+1], bh[nh*4+2], bh[nh*4+3], ba + OFF_WH);
                ldsm_x4(bl[nh*4+0], bl[nh*4+1], bl[nh*4+2], bl[nh*4+3], ba + OFF_WL);
            }
#pragma unroll
            for (int mi = 0; mi < 4; mi++) {
                uint32_t aa = stg + a_base + (uint32_t)(mi * 16 * SROW * 2) + koff;
                uint32_t ah[4], al[4];
                ldsm_x4(ah[0], ah[1], ah[2], ah[3], aa + OFF_AH);
                ldsm_x4(al[0], al[1], al[2], al[3], aa + OFF_AL);
#pragma unroll
                for (int ni = 0; ni < 4; ni++) {
                    mma_bf16(acc[mi][ni], ah, bh[ni*2], bh[ni*2+1]);
                    mma_bf16(acc[mi][ni], ah, bl[ni*2], bl[ni*2+1]);
                    mma_bf16(acc[mi][ni], al, bh[ni*2], bh[ni*2+1]);
                }
            }
        }
        __syncthreads();
    }

    // epilogue: c frag layout (m16n8): c0 (r=t/4, c=2(t%4)), c1 c+1, c2/c3 r+8
#pragma unroll
    for (int mi = 0; mi < 4; mi++) {
        int m = m0 + wm + mi * 16 + (lane >> 2);
#pragma unroll
        for (int ni = 0; ni < 4; ni++) {
            int nl = wn + ni * 8 + (lane & 3) * 2;   // local col (even)
            float b0 = bias[nl], b1 = bias[nl + 1];
            float2 o0 = make_float2(acc[mi][ni][0] + b0, acc[mi][ni][1] + b1);
            float2 o1 = make_float2(acc[mi][ni][2] + b0, acc[mi][ni][3] + b1);
            if (relu) {
                o0.x = fmaxf(o0.x, 0.f); o0.y = fmaxf(o0.y, 0.f);
                o1.x = fmaxf(o1.x, 0.f); o1.y = fmaxf(o1.y, 0.f);
            }
            *(float2*)(C + (size_t)m * ldc + ccol0 + nl)       = o0;
            *(float2*)(C + (size_t)(m + 8) * ldc + ccol0 + nl) = o1;
        }
    }
}

// ---- fused QKV projection: grid (16, 12) ----------------------------------
__global__ __launch_bounds__(256) void mma_qkv_kernel(
    const float* __restrict__ X,
    const float* __restrict__ Wq, const float* __restrict__ bq,
    const float* __restrict__ Wk, const float* __restrict__ bk,
    const float* __restrict__ Wv, const float* __restrict__ bv)
{
    int m0   = blockIdx.x * 128;
    int ng   = blockIdx.y * 128;
    int sect = ng >> 9;
    int nl   = ng & 511;
    const float* W    = (sect == 0) ? Wq : (sect == 1) ? Wk : Wv;
    const float* bias = (sect == 0) ? bq : (sect == 1) ? bk : bv;
    tc_gemm_tile(X, W, bias + nl, g_QKV, 1536, m0, nl, ng, sect < 2);
}

// ---- output projection: grid (16, 4) --------------------------------------
__global__ __launch_bounds__(256) void mma_out_kernel(
    const float* __restrict__ Wo, const float* __restrict__ bo,
    float* __restrict__ out)
{
    int m0 = blockIdx.x * 128;
    int n0 = blockIdx.y * 128;
    tc_gemm_tile(g_attn, Wo, bo + n0, out, E_DIM, m0, n0, n0, false);
}

// ---------------------------------------------------------------------------
// Per-chunk sums: KV_c[dd][m] = sum_l k_exp[l][dd] * v[l][m];  z_c[dd]
// ---------------------------------------------------------------------------
__global__ __launch_bounds__(256) void chunksum_kernel()
{
    int c  = blockIdx.x;
    int n  = c >> 3, cc = c & 7;
    int b  = n >> 3, h  = n & 7;
    int tid = threadIdx.x;

    __shared__ float kb[8][64], vb[8][64], sl[8], clv[8];

    const int dd = tid >> 1;
    const int mg = (tid & 1) << 5;
    float acc[32];
#pragma unroll
    for (int m = 0; m < 32; m++) acc[m] = 0.f;
    float zacc = 0.f;

    const int ll  = tid >> 5;
    const int off = (tid & 31) << 2;

    for (int l0 = 0; l0 < CHUNK; l0 += 8) {
        __syncthreads();
        {
            int lg  = cc * CHUNK + l0 + ll;
            int r   = lg * 2 + b;
            int col = (off < 64) ? (512 + h * 64 + off) : (1024 + h * 64 + (off - 64));
            float4 val = *(const float4*)&g_QKV[(size_t)r * 1536 + col];
            if (off < 64) *(float4*)&kb[ll][off]      = val;
            else          *(float4*)&vb[ll][off - 64] = val;
            if (tid < 8) {
                float th = ANG * (float)(cc * CHUNK + l0 + tid + 1);
                sl[tid]  = sinf(th);
                clv[tid] = cosf(th);
            }
        }
        __syncthreads();
#pragma unroll
        for (int q = 0; q < 8; q++) {
            float ke = (dd < 64) ? (sl[q] * kb[q][dd]) : (clv[q] * kb[q][dd - 64]);
            zacc += ke;
#pragma unroll
            for (int m = 0; m < 32; m++)
                acc[m] = fmaf(ke, vb[q][mg + m], acc[m]);
        }
    }
    float* st = &g_state[(size_t)c * 8192 + (size_t)dd * 64 + mg];
#pragma unroll
    for (int m = 0; m < 32; m += 4)
        *(float4*)&st[m] = make_float4(acc[m], acc[m+1], acc[m+2], acc[m+3]);
    if (mg == 0) g_z[c * 128 + dd] = zacc;
}

// ---- exclusive prefix over chunks of each sequence: grid (16, 33) ---------
__global__ __launch_bounds__(256) void scan_kernel()
{
    int n = blockIdx.x;
    if (blockIdx.y < 32) {
        int e = blockIdx.y * 256 + threadIdx.x;
        float run = 0.f;
        for (int cc = 0; cc < 8; cc++) {
            size_t idx = (size_t)(n * 8 + cc) * 8192 + e;
            float t = g_state[idx];
            g_state[idx] = run;
            run += t;
        }
    } else if (threadIdx.x < 128) {
        int e = threadIdx.x;
        float run = 0.f;
        for (int cc = 0; cc < 8; cc++) {
            int idx = (n * 8 + cc) * 128 + e;
            float t = g_z[idx];
            g_z[idx] = run;
            run += t;
        }
    }
}

// ---------------------------------------------------------------------------
// Per-chunk attention. grid: 128 blocks, 256 threads, ~167 KB dynamic smem
// ---------------------------------------------------------------------------
constexpr int TS = 132;
constexpr int VS = 68;
constexpr int WS = 129;
constexpr int SMEM_FLOATS = 64*TS + 64*TS + 128*VS + 128*WS + 4*128;
constexpr int SMEM_BYTES  = SMEM_FLOATS * 4;

__global__ __launch_bounds__(256) void chunkattn_kernel()
{
    extern __shared__ char dynsm[];
    float* sm = (float*)dynsm;
    float* sQt  = sm;
    float* sKt  = sQt + 64 * TS;
    float* sV   = sKt + 64 * TS;
    float* sW   = sV + 128 * VS;
    float* ssin = sW + 128 * WS;
    float* scos = ssin + 128;
    float* sden = scos + 128;
    float* szp  = sden + 128;

    int c  = blockIdx.x;
    int n  = c >> 3, cc = c & 7;
    int b  = n >> 3, h  = n & 7;
    int tid = threadIdx.x;

#pragma unroll
    for (int i = 0; i < 8; i++) {
        int f4 = tid + i * 256;
        int l  = f4 & 127;
        int kv = (f4 >> 7) << 2;
        int r  = (cc * CHUNK + l) * 2 + b;
        const float* base = &g_QKV[(size_t)r * 1536 + h * 64 + kv];
        float4 qv = *(const float4*)(base);
        float4 k4 = *(const float4*)(base + 512);
        float4 vv = *(const float4*)(base + 1024);
        sQt[(kv + 0) * TS + l] = qv.x; sQt[(kv + 1) * TS + l] = qv.y;
        sQt[(kv + 2) * TS + l] = qv.z; sQt[(kv + 3) * TS + l] = qv.w;
        sKt[(kv + 0) * TS + l] = k4.x; sKt[(kv + 1) * TS + l] = k4.y;
        sKt[(kv + 2) * TS + l] = k4.z; sKt[(kv + 3) * TS + l] = k4.w;
        *(float4*)&sV[l * VS + kv] = vv;
    }
    if (tid < 128) {
        float th = ANG * (float)(cc * CHUNK + tid + 1);
        ssin[tid] = sinf(th);
        scos[tid] = cosf(th);
        szp[tid]  = g_z[c * 128 + tid];
    }
    __syncthreads();

    {
        int tx = tid & 15, ty = tid >> 4;
        float accW[8][8];
#pragma unroll
        for (int i = 0; i < 8; i++)
#pragma unroll
            for (int j = 0; j < 8; j++) accW[i][j] = 0.f;

        for (int kk = 0; kk < 64; kk++) {
            float a[8], bb[8];
            *(float4*)&a[0]  = *(const float4*)&sQt[kk * TS + ty * 4];
            *(float4*)&a[4]  = *(const float4*)&sQt[kk * TS + 64 + ty * 4];
            *(float4*)&bb[0] = *(const float4*)&sKt[kk * TS + tx * 4];
            *(float4*)&bb[4] = *(const float4*)&sKt[kk * TS + 64 + tx * 4];
#pragma unroll
            for (int i = 0; i < 8; i++)
#pragma unroll
                for (int j = 0; j < 8; j++)
                    accW[i][j] = fmaf(a[i], bb[j], accW[i][j]);
        }
        float slv[8], clvv[8], sjv[8], cjv[8];
#pragma unroll
        for (int i = 0; i < 8; i++) {
            int ri = (i < 4) ? (ty * 4 + i) : (64 + ty * 4 + (i - 4));
            int cj = (i < 4) ? (tx * 4 + i) : (64 + tx * 4 + (i - 4));
            slv[i] = ssin[ri]; clvv[i] = scos[ri];
            sjv[i] = ssin[cj]; cjv[i]  = scos[cj];
        }
#pragma unroll
        for (int i = 0; i < 8; i++) {
            int l = (i < 4) ? (ty * 4 + i) : (64 + ty * 4 + (i - 4));
#pragma unroll
            for (int j = 0; j < 8; j++) {
                int jj = (j < 4) ? (tx * 4 + j) : (64 + tx * 4 + (j - 4));
                float w = (jj <= l)
                        ? accW[i][j] * (slv[i] * sjv[j] + clvv[i] * cjv[j])
                        : 0.f;
                sW[l * WS + jj] = w;
            }
        }
    }
    __syncthreads();

    {
        int l  = tid & 127;
        int mh = tid >> 7;
        int m0 = mh << 5;
        float acc2[32];
#pragma unroll
        for (int m = 0; m < 32; m++) acc2[m] = 0.f;
        float wsum = 0.f, dsum = 0.f;
        float sl = ssin[l], cl = scos[l];

#pragma unroll 2
        for (int j = 0; j < 128; j++) {
            float w = sW[l * WS + j];
            wsum += w;
#pragma unroll
            for (int m = 0; m < 32; m += 4) {
                float4 v4 = *(const float4*)&sV[j * VS + m0 + m];
                acc2[m + 0] = fmaf(w, v4.x, acc2[m + 0]);
                acc2[m + 1] = fmaf(w, v4.y, acc2[m + 1]);
                acc2[m + 2] = fmaf(w, v4.z, acc2[m + 2]);
                acc2[m + 3] = fmaf(w, v4.w, acc2[m + 3]);
            }
        }

        float* sS = sKt;
        for (int t0 = 0; t0 < 128; t0 += 64) {
            __syncthreads();
#pragma unroll
            for (int i2 = 0; i2 < 4; i2++) {
                int f4  = tid + i2 * 256;
                int ddl = f4 >> 4;
                int mv  = (f4 & 15) << 2;
                *(float4*)&sS[ddl * 64 + mv] =
                    *(const float4*)&g_state[(size_t)c * 8192 + (size_t)(t0 + ddl) * 64 + mv];
            }
            __syncthreads();
#pragma unroll 2
            for (int dd = 0; dd < 64; dd++) {
                int ddg  = t0 + dd;
                float qe = ((ddg < 64) ? sl : cl) * sQt[(ddg & 63) * TS + l];
                dsum = fmaf(qe, szp[ddg], dsum);
#pragma unroll
                for (int m = 0; m < 32; m += 4) {
                    float4 s4 = *(const float4*)&sS[dd * 64 + m0 + m];
                    acc2[m + 0] = fmaf(qe, s4.x, acc2[m + 0]);
                    acc2[m + 1] = fmaf(qe, s4.y, acc2[m + 1]);
                    acc2[m + 2] = fmaf(qe, s4.z, acc2[m + 2]);
                    acc2[m + 3] = fmaf(qe, s4.w, acc2[m + 3]);
                }
            }
        }

        if (mh == 0) sden[l] = fmaxf(wsum + dsum, EPSV);
        __syncthreads();
        float inv = 1.0f / sden[l];
        int r = (cc * CHUNK + l) * 2 + b;
        float* dst = &g_attn[(size_t)r * E_DIM + h * 64 + m0];
#pragma unroll
        for (int m = 0; m < 32; m += 4) {
            *(float4*)&dst[m] = make_float4(acc2[m] * inv, acc2[m + 1] * inv,
                                            acc2[m + 2] * inv, acc2[m + 3] * inv);
        }
    }
}

// ---------------------------------------------------------------------------
extern "C" void kernel_launch(void* const* d_in, const int* in_sizes, int n_in,
                              void* d_out, int out_size)
{
    const float* query = (const float*)d_in[0];
    const float* Wq = (const float*)d_in[1];
    const float* bq = (const float*)d_in[2];
    const float* Wk = (const float*)d_in[3];
    const float* bk = (const float*)d_in[4];
    const float* Wv = (const float*)d_in[5];
    const float* bv = (const float*)d_in[6];
    const float* Wo = (const float*)d_in[7];
    const float* bo = (const float*)d_in[8];
    float* out = (float*)d_out;

    cudaFuncSetAttribute(chunkattn_kernel,
                         cudaFuncAttributeMaxDynamicSharedMemorySize, SMEM_BYTES);
    cudaFuncSetAttribute(mma_qkv_kernel,
                         cudaFuncAttributeMaxDynamicSharedMemorySize, TC_SMEM);
    cudaFuncSetAttribute(mma_out_kernel,
                         cudaFuncAttributeMaxDynamicSharedMemorySize, TC_SMEM);

    mma_qkv_kernel<<<dim3(16, 12), 256, TC_SMEM>>>(query, Wq, bq, Wk, bk, Wv, bv);
    chunksum_kernel<<<128, 256>>>();
    scan_kernel<<<dim3(16, 33), 256>>>();
    chunkattn_kernel<<<128, 256, SMEM_BYTES>>>();
    mma_out_kernel<<<dim3(16, 4), 256, TC_SMEM>>>(Wo, bo, out);
}